// round 6
// baseline (speedup 1.0000x reference)
#include <cuda_runtime.h>
#include <cstddef>

#define H     2048
#define B     1024
#define NB    12
#define NROW  112
#define GATES 8192
#define NBLK  128
#define KC4   192                     // float4 k-prefix of each W_hh row in smem
// persist dynamic smem: wc4 (196608B) + scand (2*11*256 fl) + sdec (1824 fl)
#define SCAND_F   (2 * 11 * 256)
#define SDEC_F    1824
#define P_DSMEM   (64 * KC4 * 16 + (SCAND_F + SDEC_F) * 4)   // 226432 B

// k_pre dynamic smem
#define PRE_W_F2   (256 * 17)
#define PRE_E_F2   (56 * 17)
#define PRE_DSMEM  ((PRE_W_F2 + PRE_E_F2) * 8)

// ---------------------------------------------------------------------------
__device__ __align__(16) float g_h[2][H];
__device__ __align__(16) float g_c[H];
__device__ __align__(16) float g_emb[NROW][H];
__device__ __align__(16) float g_pre[4][NROW][GATES];
__device__ float g_part[2][12][NBLK];
__device__ unsigned g_cnt[32 * 8];

__device__ __forceinline__ float sigmoidf_(float v) { return 1.0f / (1.0f + expf(-v)); }

__device__ __forceinline__ unsigned long long pk2(float a, float b) {
    unsigned long long p;
    asm("mov.b64 %0, {%1, %2};" : "=l"(p) : "f"(a), "f"(b));
    return p;
}
__device__ __forceinline__ void fma2(unsigned long long& d,
                                     unsigned long long a, unsigned long long b) {
    asm("fma.rn.f32x2 %0, %1, %2, %0;" : "+l"(d) : "l"(a), "l"(b));
}
__device__ __forceinline__ void unpk2(unsigned long long p, float& a, float& b) {
    asm("mov.b64 {%0, %1}, %2;" : "=f"(a), "=f"(b) : "l"(p));
}

// ---------------------------------------------------------------------------
// Non-flushing grid barrier (no CCTL.IVALL): release-red arrival, acquire poll.
// 32 padded counters, 4 arrivals each. Correct because all cross-SM payloads
// move via __stcg/__ldcg (L2 point of coherence) and bar.sync gives the
// cumulativity chain into the release.
// ---------------------------------------------------------------------------
__device__ __forceinline__ void gsync(unsigned target4) {
    __syncthreads();
    if (threadIdx.x == 0) {
        asm volatile("red.release.gpu.global.add.u32 [%0], %1;"
                     :: "l"(&g_cnt[(blockIdx.x & 31) * 8]), "r"(1u) : "memory");
    }
    if (threadIdx.x < 32) {
        const unsigned* cp = &g_cnt[threadIdx.x * 8];
        unsigned v;
        while (true) {
            asm volatile("ld.acquire.gpu.global.u32 %0, [%1];" : "=r"(v) : "l"(cp) : "memory");
            if (v >= target4) break;
            __nanosleep(40);
        }
    }
    __syncthreads();
}

__global__ void k_init() {
    if (threadIdx.x < 32 * 8) g_cnt[threadIdx.x] = 0u;
}

// ---------------------------------------------------------------------------
// Gather 110 candidate embedding rows (static schedule) into g_emb.
// ---------------------------------------------------------------------------
__global__ void k_gather(const float* __restrict__ enc_act,
                         const float* __restrict__ enc_block) {
    int r = blockIdx.x;
    int u = 1, base = 0, cnt = 4;
    while (u < 22 && r >= base + cnt) { base += cnt; ++u; cnt = (u & 1) ? 4 : (u >> 1); }
    const float* src;
    if (r >= base + cnt) {
        src = enc_act;
    } else {
        int o = r - base;
        if (u & 1) src = enc_act   + ((size_t)((u - 1) >> 1) * 4        + o) * H;
        else       src = enc_block + ((size_t)((u >> 1) - 1) * (NB - 1) + o) * H;
    }
    const float4* s4 = (const float4*)src;
    float4*       d4 = (float4*)g_emb[r];
    for (int i = threadIdx.x; i < H / 4; i += 256) d4[i] = s4[i];
}

// ---------------------------------------------------------------------------
// Precompute GEMM (packed f32x2): 128 blocks x 2 tiles (known-good from R4).
// ---------------------------------------------------------------------------
__global__ __launch_bounds__(256)
void k_pre(const float* __restrict__ Wih,
           const float* __restrict__ b_ih, const float* __restrict__ b_hh) {
    extern __shared__ float2 dynp[];
    float2* Wt2 = dynp;
    float2* Es2 = dynp + PRE_W_F2;

    const int t = threadIdx.x, c = t & 31, r = t >> 5;

    for (int tile = blockIdx.x; tile < 256; tile += 128) {
        const int nb = tile & 31, mb = (tile >> 5) & 1, kb = tile >> 6;
        const int n_base = nb * 256, m_base = mb * 56, k_base = kb * 512;

        unsigned long long acc[7][8];
#pragma unroll
        for (int j = 0; j < 7; j++)
#pragma unroll
            for (int i = 0; i < 8; i++) acc[j][i] = 0ull;

        float4 wst[8];
        float4 est[2];
        {
            const float4* wsrc = (const float4*)(Wih + (size_t)(n_base + t) * H + k_base);
#pragma unroll
            for (int q = 0; q < 8; q++) wst[q] = __ldcg(&wsrc[q]);
#pragma unroll
            for (int x = 0; x < 2; x++) {
                int idx = t + 256 * x;
                if (idx < 448) {
                    int row = idx >> 3, q = idx & 7;
                    est[x] = *(const float4*)&g_emb[m_base + row][k_base + 4 * q];
                }
            }
        }

        for (int kt = 0; kt < 512; kt += 32) {
            {
                float2* wd = &Wt2[t * 17];
#pragma unroll
                for (int q = 0; q < 8; q++) {
                    wd[2 * q + 0] = make_float2(wst[q].x, wst[q].y);
                    wd[2 * q + 1] = make_float2(wst[q].z, wst[q].w);
                }
#pragma unroll
                for (int x = 0; x < 2; x++) {
                    int idx = t + 256 * x;
                    if (idx < 448) {
                        int row = idx >> 3, q = idx & 7;
                        Es2[row * 17 + 2 * q + 0] = make_float2(est[x].x, est[x].y);
                        Es2[row * 17 + 2 * q + 1] = make_float2(est[x].z, est[x].w);
                    }
                }
            }
            __syncthreads();

            if (kt + 32 < 512) {
                const int k0 = k_base + kt + 32;
                const float4* wsrc = (const float4*)(Wih + (size_t)(n_base + t) * H + k0);
#pragma unroll
                for (int q = 0; q < 8; q++) wst[q] = __ldcg(&wsrc[q]);
#pragma unroll
                for (int x = 0; x < 2; x++) {
                    int idx = t + 256 * x;
                    if (idx < 448) {
                        int row = idx >> 3, q = idx & 7;
                        est[x] = *(const float4*)&g_emb[m_base + row][k0 + 4 * q];
                    }
                }
            }

#pragma unroll
            for (int kk2 = 0; kk2 < 16; kk2++) {
                unsigned long long w2[8], e2[7];
#pragma unroll
                for (int i = 0; i < 8; i++)
                    w2[i] = *(const unsigned long long*)&Wt2[(c + 32 * i) * 17 + kk2];
#pragma unroll
                for (int j = 0; j < 7; j++)
                    e2[j] = *(const unsigned long long*)&Es2[(r * 7 + j) * 17 + kk2];
#pragma unroll
                for (int j = 0; j < 7; j++)
#pragma unroll
                    for (int i = 0; i < 8; i++)
                        fma2(acc[j][i], w2[i], e2[j]);
            }
            __syncthreads();
        }

#pragma unroll
        for (int j = 0; j < 7; j++) {
            int m = m_base + r * 7 + j;
#pragma unroll
            for (int i = 0; i < 8; i++) {
                int n = n_base + c + 32 * i;
                float lo, hi;
                unpk2(acc[j][i], lo, hi);
                float v = lo + hi;
                if (kb == 0) v += b_ih[n] + b_hh[n];
                g_pre[kb][m][n] = v;
            }
        }
        __syncthreads();
    }
}

// ---------------------------------------------------------------------------
// (dec pointer, ncls) for the decode performed at step s (0..22).
// ---------------------------------------------------------------------------
__device__ __forceinline__ const float* dec_for(int s, const float* da,
                                                const float* db, int& ncls) {
    if (s == 0) { ncls = 4; return da; }
    if (s & 1)  { int bid = (s + 1) >> 1; ncls = bid;
                  return db + (size_t)(bid - 1) * (NB - 1) * H; }
    ncls = 4; return da + (size_t)(s >> 1) * 4 * H;
}

// ---------------------------------------------------------------------------
// Persistent kernel: 128 blocks x 1024 threads, 16 hidden units per block.
// ---------------------------------------------------------------------------
__global__ __launch_bounds__(1024, 1)
void k_persist(const float* __restrict__ Whh,
               const float* __restrict__ b_ih, const float* __restrict__ b_hh,
               const float* __restrict__ dec_act, const float* __restrict__ dec_block,
               float* __restrict__ out, int out_size) {
    extern __shared__ float dyn[];
    float4* wc4   = (float4*)dyn;                    // [64][KC4]
    float*  scand = dyn + 64 * KC4 * 4;              // [2][11][256]
    float*  sdec  = scand + SCAND_F;                 // [1824]

    __shared__ float wsum[4][8][16];
    __shared__ float slog[12];
    __shared__ float sunit[16];
    __shared__ float scell[16];

    const int bid = blockIdx.x, t = threadIdx.x;
    const int lane = t & 31, warp = t >> 5;
    const int rg = t >> 8, kq = t & 255, wig = (t >> 5) & 7;
    const int j0 = bid * 16;
    const float4* W4 = (const float4*)Whh;

    // ---- startup loads (all overlap): W_hh prefix, decoder rows, step-1 cands
    for (int idx = t; idx < 64 * KC4; idx += 1024) {
        int R = idx / KC4, q = idx - R * KC4;
        size_t grow = (size_t)((R >> 4) * H + j0 + (R & 15));
        wc4[R * KC4 + q] = __ldcg(&W4[grow * (H / 4) + q]);
    }
    for (int e = t; e < SDEC_F; e += 1024) {
        int cr = e >> 4, u = e & 15;
        int off = 0, nc = 0;
        const float* dp = dec_act;
        for (int s = 0; s <= 22; s++) {
            dp = dec_for(s, dec_act, dec_block, nc);
            if (cr < off + nc) break;
            off += nc;
        }
        int cls = cr - off;
        sdec[e] = __ldcg(&dp[(size_t)cls * H + j0 + u]);
    }
    for (int idx = t; idx < 4 * 256; idx += 1024) {       // step-1 candidates, buf 1
        int cd = idx >> 8, r2 = idx & 255;
        int q = r2 >> 6, rest = r2 & 63;
        scand[11 * 256 + idx] = __ldcg(&g_pre[q][cd][(size_t)(rest >> 4) * H + j0 + (rest & 15)]);
    }

    // ---- step 0: gates = biases ----
    if (t < 16) {
        int j = j0 + t;
        float gi = b_ih[j        ] + b_hh[j        ];
        float gg = b_ih[2 * H + j] + b_hh[2 * H + j];
        float go = b_ih[3 * H + j] + b_hh[3 * H + j];
        float c2 = sigmoidf_(gi) * tanhf(gg);
        float h2 = sigmoidf_(go) * tanhf(c2);
        scell[t] = c2;
        sunit[t] = h2;
        __stcg(&g_h[0][j], h2);
    }
    __syncthreads();
    if (warp < 4) {      // step-0 decode partials (sdec rows 0..3)
        float v = (lane < 16) ? sunit[lane] * sdec[warp * 16 + lane] : 0.0f;
        v += __shfl_down_sync(0xffffffffu, v, 8);
        v += __shfl_down_sync(0xffffffffu, v, 4);
        v += __shfl_down_sync(0xffffffffu, v, 2);
        v += __shfl_down_sync(0xffffffffu, v, 1);
        if (lane == 0) __stcg(&g_part[1][warp][bid], v);
    }

    unsigned phase = 1;
    gsync(phase * 4);

    // ---- 22 fused steps ----
    int cand_base = 0, ncand = 4, doff = 4;
    for (int s = 1; s <= 22; s++) {
        const int parity = s & 1, pr = s & 1, pw = (s + 1) & 1;

        // prologue: per-class sums of the 128 block-partials -> slog (no sync;
        // ordered by the wsum barrier below)
        if (warp < ncand) {
            const float* p = g_part[pr][warp];
            float a = __ldcg(&p[lane]) + __ldcg(&p[lane + 32])
                    + __ldcg(&p[lane + 64]) + __ldcg(&p[lane + 96]);
            a += __shfl_down_sync(0xffffffffu, a, 16);
            a += __shfl_down_sync(0xffffffffu, a, 8);
            a += __shfl_down_sync(0xffffffffu, a, 4);
            a += __shfl_down_sync(0xffffffffu, a, 2);
            a += __shfl_down_sync(0xffffffffu, a, 1);
            if (lane == 0) slog[warp] = a;
        }

        // main GEMV: 16 rows (gate rg) x H; k-prefix from smem
        const float4* h4 = (const float4*)g_h[parity ^ 1];
        float acc[16];
#pragma unroll
        for (int i = 0; i < 16; i++) acc[i] = 0.0f;
        {
            float4 hv = __ldcg(&h4[kq]);
            if (wig < 6) {
#pragma unroll
                for (int rl = 0; rl < 16; rl++) {
                    float4 w = wc4[(rg * 16 + rl) * KC4 + kq];
                    acc[rl] += hv.x * w.x + hv.y * w.y + hv.z * w.z + hv.w * w.w;
                }
            } else {
#pragma unroll
                for (int rl = 0; rl < 16; rl++) {
                    float4 w = __ldcg(&W4[(size_t)(rg * H + j0 + rl) * (H / 4) + kq]);
                    acc[rl] += hv.x * w.x + hv.y * w.y + hv.z * w.z + hv.w * w.w;
                }
            }
            int k4 = kq + 256;
            float4 hv2 = __ldcg(&h4[k4]);
#pragma unroll
            for (int rl = 0; rl < 16; rl++) {
                float4 w = __ldcg(&W4[(size_t)(rg * H + j0 + rl) * (H / 4) + k4]);
                acc[rl] += hv2.x * w.x + hv2.y * w.y + hv2.z * w.z + hv2.w * w.w;
            }
        }

#pragma unroll
        for (int i = 0; i < 16; i++) {
            float a = acc[i];
            a += __shfl_down_sync(0xffffffffu, a, 16);
            a += __shfl_down_sync(0xffffffffu, a, 8);
            a += __shfl_down_sync(0xffffffffu, a, 4);
            a += __shfl_down_sync(0xffffffffu, a, 2);
            a += __shfl_down_sync(0xffffffffu, a, 1);
            if (lane == 0) wsum[rg][wig][i] = a;
        }
        __syncthreads();

        // tail: 16 threads finish reduction + argmax + pointwise (all smem)
        if (t < 16) {
            int lc = 0;
            {
                float bv = slog[0];
                for (int cc = 1; cc < ncand; cc++)
                    if (slog[cc] > bv) { bv = slog[cc]; lc = cc; }
            }
            const float* cp = scand + (s & 1) * 11 * 256 + lc * 256;
            float gi = 0.f, gf = 0.f, gg = 0.f, go = 0.f;
#pragma unroll
            for (int w = 0; w < 8; w++) {
                gi += wsum[0][w][t]; gf += wsum[1][w][t];
                gg += wsum[2][w][t]; go += wsum[3][w][t];
            }
#pragma unroll
            for (int q = 0; q < 4; q++) {
                gi += cp[q * 64      + t]; gf += cp[q * 64 + 16 + t];
                gg += cp[q * 64 + 32 + t]; go += cp[q * 64 + 48 + t];
            }
            float c2 = sigmoidf_(gf) * scell[t] + sigmoidf_(gi) * tanhf(gg);
            float h2 = sigmoidf_(go) * tanhf(c2);
            scell[t] = c2;
            sunit[t] = h2;
            __stcg(&g_h[parity][j0 + t], h2);
            if (s == 22) __stcg(&g_c[j0 + t], c2);
        }
        __syncthreads();

        // epilogue: this step's decode partials from smem decoder rows
        int ncls;
        dec_for(s, dec_act, dec_block, ncls);
        if (warp < ncls) {
            float v = (lane < 16) ? sunit[lane] * sdec[(doff + warp) * 16 + lane] : 0.0f;
            v += __shfl_down_sync(0xffffffffu, v, 8);
            v += __shfl_down_sync(0xffffffffu, v, 4);
            v += __shfl_down_sync(0xffffffffu, v, 2);
            v += __shfl_down_sync(0xffffffffu, v, 1);
            if (lane == 0) __stcg(&g_part[pw][warp][bid], v);
        }

        // prefetch next step's candidate pre-rows (overlaps the barrier)
        int nb_next = cand_base + ncand;
        if (s < 22) {
            float* dst = scand + ((s + 1) & 1) * 11 * 256;
            for (int idx = t; idx < ncls * 256; idx += 1024) {
                int cd = idx >> 8, r2 = idx & 255;
                int q = r2 >> 6, rest = r2 & 63;
                dst[idx] = __ldcg(&g_pre[q][nb_next + cd]
                                        [(size_t)(rest >> 4) * H + j0 + (rest & 15)]);
            }
        }
        cand_base = nb_next;
        ncand = ncls;
        doff += ncls;

        ++phase;
        gsync(phase * 4);
    }

    // ---- final argmax (step-22 decode partials, 4 classes) ----
    if (warp < 4) {
        const float* p = g_part[1][warp];
        float a = __ldcg(&p[lane]) + __ldcg(&p[lane + 32])
                + __ldcg(&p[lane + 64]) + __ldcg(&p[lane + 96]);
        a += __shfl_down_sync(0xffffffffu, a, 16);
        a += __shfl_down_sync(0xffffffffu, a, 8);
        a += __shfl_down_sync(0xffffffffu, a, 4);
        a += __shfl_down_sync(0xffffffffu, a, 2);
        a += __shfl_down_sync(0xffffffffu, a, 1);
        if (lane == 0) slog[warp] = a;
    }
    __syncthreads();

    int best = 0;
    {
        float bv = slog[0];
        for (int cc = 1; cc < 4; cc++)
            if (slog[cc] > bv) { bv = slog[cc]; best = cc; }
    }

    // ---- output broadcast ----
    const float fidx = (float)best;
    const long HB = (long)B * H;
    for (long i = (long)bid * 1024 + t; i < out_size; i += (long)NBLK * 1024) {
        float v;
        if (i < B)               v = fidx;
        else if (i < B + HB)     v = __ldcg(&g_h[0][(i - B) & (H - 1)]);
        else if (i < B + 2 * HB) v = __ldcg(&g_c[(i - B - HB) & (H - 1)]);
        else                     v = 0.0f;
        __stcs(out + i, v);
    }
}

// ---------------------------------------------------------------------------
extern "C" void kernel_launch(void* const* d_in, const int* in_sizes, int n_in,
                              void* d_out, int out_size) {
    (void)in_sizes; (void)n_in;
    const float* Wih       = (const float*)d_in[1];
    const float* Whh       = (const float*)d_in[2];
    const float* b_ih      = (const float*)d_in[3];
    const float* b_hh      = (const float*)d_in[4];
    const float* enc_act   = (const float*)d_in[5];
    const float* enc_block = (const float*)d_in[6];
    const float* dec_act   = (const float*)d_in[7];
    const float* dec_block = (const float*)d_in[8];

    static int attr_done = 0;
    if (!attr_done) {
        cudaFuncSetAttribute(k_persist, cudaFuncAttributeMaxDynamicSharedMemorySize, P_DSMEM);
        cudaFuncSetAttribute(k_pre, cudaFuncAttributeMaxDynamicSharedMemorySize, PRE_DSMEM);
        attr_done = 1;
    }

    k_init<<<1, 256>>>();
    k_gather<<<NROW, 256>>>(enc_act, enc_block);
    k_pre<<<128, 256, PRE_DSMEM>>>(Wih, b_ih, b_hh);
    k_persist<<<NBLK, 1024, P_DSMEM>>>(Whh, b_ih, b_hh, dec_act, dec_block,
                                       (float*)d_out, out_size);
}

// round 8
// speedup vs baseline: 1.0206x; 1.0206x over previous
#include <cuda_runtime.h>
#include <cstddef>

#define H     2048
#define B     1024
#define NB    12
#define NROW  112
#define GATES 8192
#define NBLK  256                 // persistent blocks (2/SM)
#define NTHR  512
#define KC4   172                 // float4 k-prefix of each W_hh row in smem

// persist dynamic smem layout (floats):
//   wc4   : 32 rows x KC4 float4                = 88064 B
//   scand : 2 x 11 x 128                        = 11264 B
//   sdec  : 114 x 8                             =  3648 B
//   sh4   : 512 float4                          =  8192 B
#define WC_F      (32 * KC4 * 4)
#define SCAND_F   (2 * 11 * 128)
#define SDEC_F    (114 * 8)
#define SH_OFF_F  (WC_F + SCAND_F + SDEC_F)
#define P_DSMEM   ((SH_OFF_F + 512 * 4) * 4)    // 111168 B

// k_pre dynamic smem
#define PRE_W_F2   (256 * 17)
#define PRE_E_F2   (56 * 17)
#define PRE_DSMEM  ((PRE_W_F2 + PRE_E_F2) * 8)

// ---------------------------------------------------------------------------
__device__ __align__(16) float g_h[2][H];
__device__ __align__(16) float g_c[H];
__device__ __align__(16) float g_emb[NROW][H];
__device__ __align__(16) float g_pre[4][NROW][GATES];
__device__ float g_part[2][12][NBLK];
__device__ unsigned g_cnt[32 * 8];

__device__ __forceinline__ float sigmoidf_(float v) { return 1.0f / (1.0f + expf(-v)); }

__device__ __forceinline__ unsigned long long pk2(float a, float b) {
    unsigned long long p;
    asm("mov.b64 %0, {%1, %2};" : "=l"(p) : "f"(a), "f"(b));
    return p;
}
__device__ __forceinline__ void fma2(unsigned long long& d,
                                     unsigned long long a, unsigned long long b) {
    asm("fma.rn.f32x2 %0, %1, %2, %0;" : "+l"(d) : "l"(a), "l"(b));
}
__device__ __forceinline__ void unpk2(unsigned long long p, float& a, float& b) {
    asm("mov.b64 {%0, %1}, %2;" : "=f"(a), "=f"(b) : "l"(p));
}

// ---------------------------------------------------------------------------
// Non-flushing grid barrier: release-red arrival, acquire poll.
// 32 padded counters, NBLK/32 = 8 arrivals each.
// ---------------------------------------------------------------------------
__device__ __forceinline__ void gsync(unsigned target8) {
    __syncthreads();
    if (threadIdx.x == 0) {
        asm volatile("red.release.gpu.global.add.u32 [%0], %1;"
                     :: "l"(&g_cnt[(blockIdx.x & 31) * 8]), "r"(1u) : "memory");
    }
    if (threadIdx.x < 32) {
        const unsigned* cp = &g_cnt[threadIdx.x * 8];
        unsigned v;
        while (true) {
            asm volatile("ld.acquire.gpu.global.u32 %0, [%1];" : "=r"(v) : "l"(cp) : "memory");
            if (v >= target8) break;
            __nanosleep(40);
        }
    }
    __syncthreads();
}

__global__ void k_init() {
    if (threadIdx.x < 32 * 8) g_cnt[threadIdx.x] = 0u;
}

// ---------------------------------------------------------------------------
// Gather 110 candidate embedding rows (static schedule) into g_emb.
// ---------------------------------------------------------------------------
__global__ void k_gather(const float* __restrict__ enc_act,
                         const float* __restrict__ enc_block) {
    int r = blockIdx.x;
    int u = 1, base = 0, cnt = 4;
    while (u < 22 && r >= base + cnt) { base += cnt; ++u; cnt = (u & 1) ? 4 : (u >> 1); }
    const float* src;
    if (r >= base + cnt) {
        src = enc_act;
    } else {
        int o = r - base;
        if (u & 1) src = enc_act   + ((size_t)((u - 1) >> 1) * 4        + o) * H;
        else       src = enc_block + ((size_t)((u >> 1) - 1) * (NB - 1) + o) * H;
    }
    const float4* s4 = (const float4*)src;
    float4*       d4 = (float4*)g_emb[r];
    for (int i = threadIdx.x; i < H / 4; i += 256) d4[i] = s4[i];
}

// ---------------------------------------------------------------------------
// Precompute GEMM (packed f32x2): unchanged known-good.
// ---------------------------------------------------------------------------
__global__ __launch_bounds__(256)
void k_pre(const float* __restrict__ Wih,
           const float* __restrict__ b_ih, const float* __restrict__ b_hh) {
    extern __shared__ float2 dynp[];
    float2* Wt2 = dynp;
    float2* Es2 = dynp + PRE_W_F2;

    const int t = threadIdx.x, c = t & 31, r = t >> 5;

    for (int tile = blockIdx.x; tile < 256; tile += 128) {
        const int nb = tile & 31, mb = (tile >> 5) & 1, kb = tile >> 6;
        const int n_base = nb * 256, m_base = mb * 56, k_base = kb * 512;

        unsigned long long acc[7][8];
#pragma unroll
        for (int j = 0; j < 7; j++)
#pragma unroll
            for (int i = 0; i < 8; i++) acc[j][i] = 0ull;

        float4 wst[8];
        float4 est[2];
        {
            const float4* wsrc = (const float4*)(Wih + (size_t)(n_base + t) * H + k_base);
#pragma unroll
            for (int q = 0; q < 8; q++) wst[q] = __ldcg(&wsrc[q]);
#pragma unroll
            for (int x = 0; x < 2; x++) {
                int idx = t + 256 * x;
                if (idx < 448) {
                    int row = idx >> 3, q = idx & 7;
                    est[x] = *(const float4*)&g_emb[m_base + row][k_base + 4 * q];
                }
            }
        }

        for (int kt = 0; kt < 512; kt += 32) {
            {
                float2* wd = &Wt2[t * 17];
#pragma unroll
                for (int q = 0; q < 8; q++) {
                    wd[2 * q + 0] = make_float2(wst[q].x, wst[q].y);
                    wd[2 * q + 1] = make_float2(wst[q].z, wst[q].w);
                }
#pragma unroll
                for (int x = 0; x < 2; x++) {
                    int idx = t + 256 * x;
                    if (idx < 448) {
                        int row = idx >> 3, q = idx & 7;
                        Es2[row * 17 + 2 * q + 0] = make_float2(est[x].x, est[x].y);
                        Es2[row * 17 + 2 * q + 1] = make_float2(est[x].z, est[x].w);
                    }
                }
            }
            __syncthreads();

            if (kt + 32 < 512) {
                const int k0 = k_base + kt + 32;
                const float4* wsrc = (const float4*)(Wih + (size_t)(n_base + t) * H + k0);
#pragma unroll
                for (int q = 0; q < 8; q++) wst[q] = __ldcg(&wsrc[q]);
#pragma unroll
                for (int x = 0; x < 2; x++) {
                    int idx = t + 256 * x;
                    if (idx < 448) {
                        int row = idx >> 3, q = idx & 7;
                        est[x] = *(const float4*)&g_emb[m_base + row][k0 + 4 * q];
                    }
                }
            }

#pragma unroll
            for (int kk2 = 0; kk2 < 16; kk2++) {
                unsigned long long w2[8], e2[7];
#pragma unroll
                for (int i = 0; i < 8; i++)
                    w2[i] = *(const unsigned long long*)&Wt2[(c + 32 * i) * 17 + kk2];
#pragma unroll
                for (int j = 0; j < 7; j++)
                    e2[j] = *(const unsigned long long*)&Es2[(r * 7 + j) * 17 + kk2];
#pragma unroll
                for (int j = 0; j < 7; j++)
#pragma unroll
                    for (int i = 0; i < 8; i++)
                        fma2(acc[j][i], w2[i], e2[j]);
            }
            __syncthreads();
        }

#pragma unroll
        for (int j = 0; j < 7; j++) {
            int m = m_base + r * 7 + j;
#pragma unroll
            for (int i = 0; i < 8; i++) {
                int n = n_base + c + 32 * i;
                float lo, hi;
                unpk2(acc[j][i], lo, hi);
                float v = lo + hi;
                if (kb == 0) v += b_ih[n] + b_hh[n];
                g_pre[kb][m][n] = v;
            }
        }
        __syncthreads();
    }
}

// ---------------------------------------------------------------------------
__device__ __forceinline__ const float* dec_for(int s, const float* da,
                                                const float* db, int& ncls) {
    if (s == 0) { ncls = 4; return da; }
    if (s & 1)  { int bid = (s + 1) >> 1; ncls = bid;
                  return db + (size_t)(bid - 1) * (NB - 1) * H; }
    ncls = 4; return da + (size_t)(s >> 1) * 4 * H;
}

// ---------------------------------------------------------------------------
// Persistent kernel: 256 blocks x 512 threads (2/SM, 64 warps/SM).
// Block owns 8 hidden units = 32 W_hh rows (row = gate*8 + unit).
// Warp w computes rows 2w and 2w+1 fully; lane l covers k-slices
// {l+32j : j=0..15} (float4 granularity), j<6ish from smem, rest L2.
// ---------------------------------------------------------------------------
__global__ __launch_bounds__(NTHR, 2)
void k_persist(const float* __restrict__ Whh,
               const float* __restrict__ b_ih, const float* __restrict__ b_hh,
               const float* __restrict__ dec_act, const float* __restrict__ dec_block,
               float* __restrict__ out, int out_size) {
    extern __shared__ float dyn[];
    float4* wc4   = (float4*)dyn;                    // [32][KC4]
    float*  scand = dyn + WC_F;                      // [2][11][128]
    float*  sdec  = scand + SCAND_F;                 // [114][8]
    float4* sh4   = (float4*)(dyn + SH_OFF_F);       // [512] staged h

    __shared__ float sg[32];      // per-row GEMV results
    __shared__ float slog[12];
    __shared__ float sunit[8];
    __shared__ float scell[8];

    const int bid = blockIdx.x, t = threadIdx.x;
    const int lane = t & 31, warp = t >> 5;
    const int j0 = bid * 8;
    const float4* W4 = (const float4*)Whh;

    // rows owned by this warp
    const int r0 = 2 * warp, r1 = 2 * warp + 1;
    const int gte = r0 >> 3, u0 = r0 & 7;            // r1 = same gate, u0+1
    const float4* wg0 = W4 + (size_t)(gte * H + j0 + u0) * (H / 4);
    const float4* wg1 = wg0 + (H / 4);

    // ---- startup loads ----
    for (int idx = t; idx < 32 * KC4; idx += NTHR) {
        int R = idx / KC4, q = idx - R * KC4;
        size_t grow = (size_t)((R >> 3) * H + j0 + (R & 7));
        wc4[R * KC4 + q] = __ldcg(&W4[grow * (H / 4) + q]);
    }
    for (int e = t; e < SDEC_F; e += NTHR) {
        int cr = e >> 3, u = e & 7;
        int off = 0, nc = 0;
        const float* dp = dec_act;
        for (int s = 0; s <= 22; s++) {
            dp = dec_for(s, dec_act, dec_block, nc);
            if (cr < off + nc) break;
            off += nc;
        }
        int cls = cr - off;
        sdec[e] = __ldcg(&dp[(size_t)cls * H + j0 + u]);
    }
    for (int idx = t; idx < 4 * 128; idx += NTHR) {   // step-1 candidates, buf 1
        int cd = idx >> 7, r2 = idx & 127;
        int q = r2 >> 5, rest = r2 & 31;
        scand[11 * 128 + idx] =
            __ldcg(&g_pre[q][cd][(size_t)(rest >> 3) * H + j0 + (rest & 7)]);
    }

    // ---- step 0: gates = biases ----
    if (t < 8) {
        int j = j0 + t;
        float gi = b_ih[j        ] + b_hh[j        ];
        float gg = b_ih[2 * H + j] + b_hh[2 * H + j];
        float go = b_ih[3 * H + j] + b_hh[3 * H + j];
        float c2 = sigmoidf_(gi) * tanhf(gg);
        float h2 = sigmoidf_(go) * tanhf(c2);
        scell[t] = c2;
        sunit[t] = h2;
        __stcg(&g_h[0][j], h2);
    }
    __syncthreads();
    if (warp < 4) {
        float v = (lane < 8) ? sunit[lane] * sdec[warp * 8 + lane] : 0.0f;
        v += __shfl_down_sync(0xffffffffu, v, 4);
        v += __shfl_down_sync(0xffffffffu, v, 2);
        v += __shfl_down_sync(0xffffffffu, v, 1);
        if (lane == 0) __stcg(&g_part[1][warp][bid], v);
    }

    unsigned phase = 1;
    gsync(phase * 8);

    // ---- 22 fused steps ----
    int cand_base = 0, ncand = 4, doff = 4;
    for (int s = 1; s <= 22; s++) {
        const int parity = s & 1, pr = s & 1, pw = (s + 1) & 1;

        // stage h into smem (512 threads x 1 float4)
        sh4[t] = __ldcg(&((const float4*)g_h[parity ^ 1])[t]);

        // prologue: per-class sums of 256 block-partials (warp per class)
        if (warp < ncand) {
            const float* p = g_part[pr][warp];
            float a = 0.0f;
#pragma unroll
            for (int i = 0; i < 8; i++) a += __ldcg(&p[lane + 32 * i]);
            a += __shfl_down_sync(0xffffffffu, a, 16);
            a += __shfl_down_sync(0xffffffffu, a, 8);
            a += __shfl_down_sync(0xffffffffu, a, 4);
            a += __shfl_down_sync(0xffffffffu, a, 2);
            a += __shfl_down_sync(0xffffffffu, a, 1);
            if (lane == 0) slog[warp] = a;
        }
        __syncthreads();

        // GEMV: warp computes rows r0, r1 fully
        float a0 = 0.0f, a1 = 0.0f;
#pragma unroll
        for (int j = 0; j < 16; j++) {
            const int idx = lane + 32 * j;
            float4 hv = sh4[idx];
            float4 w0, w1;
            if (idx < KC4) {
                w0 = wc4[r0 * KC4 + idx];
                w1 = wc4[r1 * KC4 + idx];
            } else {
                w0 = __ldcg(&wg0[idx]);
                w1 = __ldcg(&wg1[idx]);
            }
            a0 += hv.x * w0.x + hv.y * w0.y + hv.z * w0.z + hv.w * w0.w;
            a1 += hv.x * w1.x + hv.y * w1.y + hv.z * w1.z + hv.w * w1.w;
        }
        a0 += __shfl_down_sync(0xffffffffu, a0, 16);
        a1 += __shfl_down_sync(0xffffffffu, a1, 16);
        a0 += __shfl_down_sync(0xffffffffu, a0, 8);
        a1 += __shfl_down_sync(0xffffffffu, a1, 8);
        a0 += __shfl_down_sync(0xffffffffu, a0, 4);
        a1 += __shfl_down_sync(0xffffffffu, a1, 4);
        a0 += __shfl_down_sync(0xffffffffu, a0, 2);
        a1 += __shfl_down_sync(0xffffffffu, a1, 2);
        a0 += __shfl_down_sync(0xffffffffu, a0, 1);
        a1 += __shfl_down_sync(0xffffffffu, a1, 1);
        if (lane == 0) { sg[r0] = a0; sg[r1] = a1; }
        __syncthreads();

        // tail: 8 threads do argmax + gate math (pure smem)
        if (t < 8) {
            int lc = 0;
            {
                float bv = slog[0];
                for (int cc = 1; cc < ncand; cc++)
                    if (slog[cc] > bv) { bv = slog[cc]; lc = cc; }
            }
            const float* cp = scand + (s & 1) * 11 * 128 + lc * 128;
            float gi = sg[t], gf = sg[8 + t], gg = sg[16 + t], go = sg[24 + t];
#pragma unroll
            for (int q = 0; q < 4; q++) {
                gi += cp[q * 32      + t]; gf += cp[q * 32 +  8 + t];
                gg += cp[q * 32 + 16 + t]; go += cp[q * 32 + 24 + t];
            }
            float c2 = sigmoidf_(gf) * scell[t] + sigmoidf_(gi) * tanhf(gg);
            float h2 = sigmoidf_(go) * tanhf(c2);
            scell[t] = c2;
            sunit[t] = h2;
            __stcg(&g_h[parity][j0 + t], h2);
            if (s == 22) __stcg(&g_c[j0 + t], c2);
        }
        __syncthreads();

        // epilogue: decode partials from smem decoder rows
        int ncls;
        dec_for(s, dec_act, dec_block, ncls);
        if (warp < ncls) {
            float v = (lane < 8) ? sunit[lane] * sdec[(doff + warp) * 8 + lane] : 0.0f;
            v += __shfl_down_sync(0xffffffffu, v, 4);
            v += __shfl_down_sync(0xffffffffu, v, 2);
            v += __shfl_down_sync(0xffffffffu, v, 1);
            if (lane == 0) __stcg(&g_part[pw][warp][bid], v);
        }

        // prefetch next step's candidate pre-rows (overlaps barrier)
        int nb_next = cand_base + ncand;
        if (s < 22) {
            float* dst = scand + ((s + 1) & 1) * 11 * 128;
            for (int idx = t; idx < ncls * 128; idx += NTHR) {
                int cd = idx >> 7, r2 = idx & 127;
                int q = r2 >> 5, rest = r2 & 31;
                dst[idx] = __ldcg(&g_pre[q][nb_next + cd]
                                        [(size_t)(rest >> 3) * H + j0 + (rest & 7)]);
            }
        }
        cand_base = nb_next;
        ncand = ncls;
        doff += ncls;

        ++phase;
        gsync(phase * 8);
    }

    // ---- final argmax ----
    if (warp < 4) {
        const float* p = g_part[1][warp];
        float a = 0.0f;
#pragma unroll
        for (int i = 0; i < 8; i++) a += __ldcg(&p[lane + 32 * i]);
        a += __shfl_down_sync(0xffffffffu, a, 16);
        a += __shfl_down_sync(0xffffffffu, a, 8);
        a += __shfl_down_sync(0xffffffffu, a, 4);
        a += __shfl_down_sync(0xffffffffu, a, 2);
        a += __shfl_down_sync(0xffffffffu, a, 1);
        if (lane == 0) slog[warp] = a;
    }
    __syncthreads();

    int best = 0;
    {
        float bv = slog[0];
        for (int cc = 1; cc < 4; cc++)
            if (slog[cc] > bv) { bv = slog[cc]; best = cc; }
    }

    // ---- output broadcast ----
    const float fidx = (float)best;
    const long HB = (long)B * H;
    for (long i = (long)bid * NTHR + t; i < out_size; i += (long)NBLK * NTHR) {
        float v;
        if (i < B)               v = fidx;
        else if (i < B + HB)     v = __ldcg(&g_h[0][(i - B) & (H - 1)]);
        else if (i < B + 2 * HB) v = __ldcg(&g_c[(i - B - HB) & (H - 1)]);
        else                     v = 0.0f;
        __stcs(out + i, v);
    }
}

// ---------------------------------------------------------------------------
extern "C" void kernel_launch(void* const* d_in, const int* in_sizes, int n_in,
                              void* d_out, int out_size) {
    (void)in_sizes; (void)n_in;
    const float* Wih       = (const float*)d_in[1];
    const float* Whh       = (const float*)d_in[2];
    const float* b_ih      = (const float*)d_in[3];
    const float* b_hh      = (const float*)d_in[4];
    const float* enc_act   = (const float*)d_in[5];
    const float* enc_block = (const float*)d_in[6];
    const float* dec_act   = (const float*)d_in[7];
    const float* dec_block = (const float*)d_in[8];

    static int attr_done = 0;
    if (!attr_done) {
        cudaFuncSetAttribute(k_persist, cudaFuncAttributeMaxDynamicSharedMemorySize, P_DSMEM);
        cudaFuncSetAttribute(k_pre, cudaFuncAttributeMaxDynamicSharedMemorySize, PRE_DSMEM);
        attr_done = 1;
    }

    k_init<<<1, 256>>>();
    k_gather<<<NROW, 256>>>(enc_act, enc_block);
    k_pre<<<128, 256, PRE_DSMEM>>>(Wih, b_ih, b_hh);
    k_persist<<<NBLK, NTHR, P_DSMEM>>>(Whh, b_ih, b_hh, dec_act, dec_block,
                                       (float*)d_out, out_size);
}

// round 9
// speedup vs baseline: 1.1285x; 1.1058x over previous
#include <cuda_runtime.h>
#include <cstddef>
#include <cstdint>

#define H     2048
#define B     1024
#define NB    12
#define NROW  112
#define GATES 8192
#define NBLK  128                 // persistent blocks (1/SM)
#define NTHR  512
#define KC4   192                 // float4 k-prefix of each W_hh row in smem

// persist dynamic smem layout (floats):
//   wc4   : 64 rows x KC4 float4   = 49152 floats (196608 B)
//   scand : 2 x 704                =  1408 floats
//   sdec  : 114 x 16               =  1824 floats
//   sh4   : 512 float4             =  2048 floats
#define WC_F      (64 * KC4 * 4)
#define SCAND_F   (2 * 704)
#define SDEC_F    (114 * 16)
#define SH_OFF_F  (WC_F + SCAND_F + SDEC_F)
#define P_DSMEM   ((SH_OFF_F + 2048) * 4)       // 217728 B

// k_pre dynamic smem
#define PRE_W_F2   (256 * 17)
#define PRE_E_F2   (56 * 17)
#define PRE_DSMEM  ((PRE_W_F2 + PRE_E_F2) * 8)

// ---------------------------------------------------------------------------
__device__ __align__(16) float g_h[2][H];
__device__ __align__(16) float g_c[H];
__device__ __align__(16) float g_emb[NROW][H];
__device__ __align__(16) float g_pre[4][NROW][GATES];   // k-quarter partials
__device__ __align__(16) float g_preR[NROW][GATES];     // reduced (+biases)
__device__ float g_part[2][12][NBLK];
__device__ unsigned g_cnt[32 * 8];

__device__ __forceinline__ float sigmoidf_(float v) { return 1.0f / (1.0f + expf(-v)); }

__device__ __forceinline__ unsigned long long pk2(float a, float b) {
    unsigned long long p;
    asm("mov.b64 %0, {%1, %2};" : "=l"(p) : "f"(a), "f"(b));
    return p;
}
__device__ __forceinline__ void fma2(unsigned long long& d,
                                     unsigned long long a, unsigned long long b) {
    asm("fma.rn.f32x2 %0, %1, %2, %0;" : "+l"(d) : "l"(a), "l"(b));
}
__device__ __forceinline__ void unpk2(unsigned long long p, float& a, float& b) {
    asm("mov.b64 {%0, %1}, %2;" : "=f"(a), "=f"(b) : "l"(p));
}

__device__ __forceinline__ void cpasync16(const float* smem_dst, const float* gsrc) {
    uint32_t d = (uint32_t)__cvta_generic_to_shared(smem_dst);
    asm volatile("cp.async.cg.shared.global [%0], [%1], 16;" :: "r"(d), "l"(gsrc));
}

// ---------------------------------------------------------------------------
// Non-flushing grid barrier: 32 padded counters, NBLK/32 = 4 arrivals each.
// ---------------------------------------------------------------------------
__device__ __forceinline__ void gsync(unsigned target4) {
    __syncthreads();
    if (threadIdx.x == 0) {
        asm volatile("red.release.gpu.global.add.u32 [%0], %1;"
                     :: "l"(&g_cnt[(blockIdx.x & 31) * 8]), "r"(1u) : "memory");
    }
    if (threadIdx.x < 32) {
        const unsigned* cp = &g_cnt[threadIdx.x * 8];
        unsigned v;
        while (true) {
            asm volatile("ld.acquire.gpu.global.u32 %0, [%1];" : "=r"(v) : "l"(cp) : "memory");
            if (v >= target4) break;
            __nanosleep(40);
        }
    }
    __syncthreads();
}

__global__ void k_init() {
    if (threadIdx.x < 32 * 8) g_cnt[threadIdx.x] = 0u;
}

// ---------------------------------------------------------------------------
__global__ void k_gather(const float* __restrict__ enc_act,
                         const float* __restrict__ enc_block) {
    int r = blockIdx.x;
    int u = 1, base = 0, cnt = 4;
    while (u < 22 && r >= base + cnt) { base += cnt; ++u; cnt = (u & 1) ? 4 : (u >> 1); }
    const float* src;
    if (r >= base + cnt) {
        src = enc_act;
    } else {
        int o = r - base;
        if (u & 1) src = enc_act   + ((size_t)((u - 1) >> 1) * 4        + o) * H;
        else       src = enc_block + ((size_t)((u >> 1) - 1) * (NB - 1) + o) * H;
    }
    const float4* s4 = (const float4*)src;
    float4*       d4 = (float4*)g_emb[r];
    for (int i = threadIdx.x; i < H / 4; i += 256) d4[i] = s4[i];
}

// ---------------------------------------------------------------------------
// Precompute GEMM (packed f32x2): unchanged known-good.
// ---------------------------------------------------------------------------
__global__ __launch_bounds__(256)
void k_pre(const float* __restrict__ Wih,
           const float* __restrict__ b_ih, const float* __restrict__ b_hh) {
    extern __shared__ float2 dynp[];
    float2* Wt2 = dynp;
    float2* Es2 = dynp + PRE_W_F2;

    const int t = threadIdx.x, c = t & 31, r = t >> 5;

    for (int tile = blockIdx.x; tile < 256; tile += 128) {
        const int nb = tile & 31, mb = (tile >> 5) & 1, kb = tile >> 6;
        const int n_base = nb * 256, m_base = mb * 56, k_base = kb * 512;

        unsigned long long acc[7][8];
#pragma unroll
        for (int j = 0; j < 7; j++)
#pragma unroll
            for (int i = 0; i < 8; i++) acc[j][i] = 0ull;

        float4 wst[8];
        float4 est[2];
        {
            const float4* wsrc = (const float4*)(Wih + (size_t)(n_base + t) * H + k_base);
#pragma unroll
            for (int q = 0; q < 8; q++) wst[q] = __ldcg(&wsrc[q]);
#pragma unroll
            for (int x = 0; x < 2; x++) {
                int idx = t + 256 * x;
                if (idx < 448) {
                    int row = idx >> 3, q = idx & 7;
                    est[x] = *(const float4*)&g_emb[m_base + row][k_base + 4 * q];
                }
            }
        }

        for (int kt = 0; kt < 512; kt += 32) {
            {
                float2* wd = &Wt2[t * 17];
#pragma unroll
                for (int q = 0; q < 8; q++) {
                    wd[2 * q + 0] = make_float2(wst[q].x, wst[q].y);
                    wd[2 * q + 1] = make_float2(wst[q].z, wst[q].w);
                }
#pragma unroll
                for (int x = 0; x < 2; x++) {
                    int idx = t + 256 * x;
                    if (idx < 448) {
                        int row = idx >> 3, q = idx & 7;
                        Es2[row * 17 + 2 * q + 0] = make_float2(est[x].x, est[x].y);
                        Es2[row * 17 + 2 * q + 1] = make_float2(est[x].z, est[x].w);
                    }
                }
            }
            __syncthreads();

            if (kt + 32 < 512) {
                const int k0 = k_base + kt + 32;
                const float4* wsrc = (const float4*)(Wih + (size_t)(n_base + t) * H + k0);
#pragma unroll
                for (int q = 0; q < 8; q++) wst[q] = __ldcg(&wsrc[q]);
#pragma unroll
                for (int x = 0; x < 2; x++) {
                    int idx = t + 256 * x;
                    if (idx < 448) {
                        int row = idx >> 3, q = idx & 7;
                        est[x] = *(const float4*)&g_emb[m_base + row][k0 + 4 * q];
                    }
                }
            }

#pragma unroll
            for (int kk2 = 0; kk2 < 16; kk2++) {
                unsigned long long w2[8], e2[7];
#pragma unroll
                for (int i = 0; i < 8; i++)
                    w2[i] = *(const unsigned long long*)&Wt2[(c + 32 * i) * 17 + kk2];
#pragma unroll
                for (int j = 0; j < 7; j++)
                    e2[j] = *(const unsigned long long*)&Es2[(r * 7 + j) * 17 + kk2];
#pragma unroll
                for (int j = 0; j < 7; j++)
#pragma unroll
                    for (int i = 0; i < 8; i++)
                        fma2(acc[j][i], w2[i], e2[j]);
            }
            __syncthreads();
        }

#pragma unroll
        for (int j = 0; j < 7; j++) {
            int m = m_base + r * 7 + j;
#pragma unroll
            for (int i = 0; i < 8; i++) {
                int n = n_base + c + 32 * i;
                float lo, hi;
                unpk2(acc[j][i], lo, hi);
                float v = lo + hi;
                if (kb == 0) v += b_ih[n] + b_hh[n];
                g_pre[kb][m][n] = v;
            }
        }
        __syncthreads();
    }
}

// ---------------------------------------------------------------------------
// Reduce the 4 k-quarter partials into g_preR (deterministic order).
// ---------------------------------------------------------------------------
__global__ __launch_bounds__(1024)
void k_reduce() {
    int i = blockIdx.x * 2048 + threadIdx.x;
#pragma unroll
    for (int q = 0; q < 2; q++, i += 1024) {
        int m = i >> 13, n = i & (GATES - 1);
        float v = ((g_pre[0][m][n] + g_pre[1][m][n]) + g_pre[2][m][n]) + g_pre[3][m][n];
        g_preR[m][n] = v;
    }
}

// ---------------------------------------------------------------------------
__device__ __forceinline__ const float* dec_for(int s, const float* da,
                                                const float* db, int& ncls) {
    if (s == 0) { ncls = 4; return da; }
    if (s & 1)  { int bid = (s + 1) >> 1; ncls = bid;
                  return db + (size_t)(bid - 1) * (NB - 1) * H; }
    ncls = 4; return da + (size_t)(s >> 1) * 4 * H;
}

// ---------------------------------------------------------------------------
// Persistent kernel: 128 blocks x 512 threads (1/SM, 128 regs/thread).
// Block owns 16 hidden units = 64 W_hh rows (row = gate*16 + unit).
// Warp w owns rows 4w..4w+3; lane covers float4 k-slices lane+32j.
// j < 6 from smem cache (KC4=192), j = 6..15 streamed from L2 with deep MLP.
// ---------------------------------------------------------------------------
__global__ __launch_bounds__(NTHR, 1)
void k_persist(const float* __restrict__ Whh,
               const float* __restrict__ b_ih, const float* __restrict__ b_hh,
               const float* __restrict__ dec_act, const float* __restrict__ dec_block,
               float* __restrict__ out, int out_size) {
    extern __shared__ float dyn[];
    float4* wc4   = (float4*)dyn;                    // [64][KC4]
    float*  scand = dyn + WC_F;                      // [2][704] (11 cands x 64)
    float*  sdec  = scand + SCAND_F;                 // [114][16]
    float4* sh4   = (float4*)(dyn + SH_OFF_F);       // [512] staged h

    __shared__ float sg[64];
    __shared__ float slog[12];
    __shared__ float sunit[16];
    __shared__ float scell[16];

    const int bid = blockIdx.x, t = threadIdx.x;
    const int lane = t & 31, warp = t >> 5;
    const int j0 = bid * 16;
    const float4* W4 = (const float4*)Whh;

    // warp's 4 rows: all in gate (warp>>2), units (warp&3)*4 .. +3
    const int wrow = warp * 4;
    const int gte = warp >> 2;
    const int un0 = (warp & 3) * 4;
    const float4* wp0 = W4 + (size_t)(gte * H + j0 + un0 + 0) * (H / 4);
    const float4* wp1 = W4 + (size_t)(gte * H + j0 + un0 + 1) * (H / 4);
    const float4* wp2 = W4 + (size_t)(gte * H + j0 + un0 + 2) * (H / 4);
    const float4* wp3 = W4 + (size_t)(gte * H + j0 + un0 + 3) * (H / 4);

    // ---- startup loads ----
    for (int idx = t; idx < 64 * KC4; idx += NTHR) {
        int R = idx / KC4, q = idx - R * KC4;
        size_t grow = (size_t)((R >> 4) * H + j0 + (R & 15));
        wc4[R * KC4 + q] = __ldcg(&W4[grow * (H / 4) + q]);
    }
    for (int e = t; e < SDEC_F; e += NTHR) {
        int cr = e >> 4, u = e & 15;
        int off = 0, nc = 0;
        const float* dp = dec_act;
        for (int s = 0; s <= 22; s++) {
            dp = dec_for(s, dec_act, dec_block, nc);
            if (cr < off + nc) break;
            off += nc;
        }
        int cls = cr - off;
        sdec[e] = __ldcg(&dp[(size_t)cls * H + j0 + u]);
    }
    for (int idx = t; idx < 4 * 64; idx += NTHR) {       // step-1 candidates, buf 1
        int cd = idx >> 6, c = idx & 63;
        int g = c >> 4, u = c & 15;
        scand[704 + cd * 64 + c] = __ldcg(&g_preR[cd][(size_t)g * H + j0 + u]);
    }

    // ---- step 0: gates = biases ----
    if (t < 16) {
        int j = j0 + t;
        float gi = b_ih[j        ] + b_hh[j        ];
        float gg = b_ih[2 * H + j] + b_hh[2 * H + j];
        float go = b_ih[3 * H + j] + b_hh[3 * H + j];
        float c2 = sigmoidf_(gi) * tanhf(gg);
        float h2 = sigmoidf_(go) * tanhf(c2);
        scell[t] = c2;
        sunit[t] = h2;
        __stcg(&g_h[0][j], h2);
    }
    __syncthreads();
    if (warp < 4) {
        float v = (lane < 16) ? sunit[lane] * sdec[warp * 16 + lane] : 0.0f;
        v += __shfl_down_sync(0xffffffffu, v, 8);
        v += __shfl_down_sync(0xffffffffu, v, 4);
        v += __shfl_down_sync(0xffffffffu, v, 2);
        v += __shfl_down_sync(0xffffffffu, v, 1);
        if (lane == 0) __stcg(&g_part[1][warp][bid], v);
    }

    unsigned phase = 1;
    gsync(phase * 4);

    // ---- 22 fused steps ----
    int cand_base = 0, ncand = 4, doff = 4;
    for (int s = 1; s <= 22; s++) {
        const int parity = s & 1, pr = s & 1, pw = (s + 1) & 1;

        // stage h into smem (512 threads x 1 float4; latency hidden by prologue)
        sh4[t] = __ldcg(&((const float4*)g_h[parity ^ 1])[t]);

        // prologue: per-class sums of 128 block-partials (warp per class)
        if (warp < ncand) {
            const float* p = g_part[pr][warp];
            float a = __ldcg(&p[lane]) + __ldcg(&p[lane + 32])
                    + __ldcg(&p[lane + 64]) + __ldcg(&p[lane + 96]);
            a += __shfl_down_sync(0xffffffffu, a, 16);
            a += __shfl_down_sync(0xffffffffu, a, 8);
            a += __shfl_down_sync(0xffffffffu, a, 4);
            a += __shfl_down_sync(0xffffffffu, a, 2);
            a += __shfl_down_sync(0xffffffffu, a, 1);
            if (lane == 0) slog[warp] = a;
        }
        __syncthreads();

        // GEMV: warp computes rows wrow..wrow+3 fully
        float a0 = 0.f, a1 = 0.f, a2 = 0.f, a3 = 0.f;

        // streamed region first (deep MLP with 128 regs)
#pragma unroll
        for (int j = 6; j < 16; j++) {
            const int idx = lane + 32 * j;
            float4 w0 = __ldcg(&wp0[idx]);
            float4 w1 = __ldcg(&wp1[idx]);
            float4 w2 = __ldcg(&wp2[idx]);
            float4 w3 = __ldcg(&wp3[idx]);
            float4 hv = sh4[idx];
            a0 += hv.x * w0.x + hv.y * w0.y + hv.z * w0.z + hv.w * w0.w;
            a1 += hv.x * w1.x + hv.y * w1.y + hv.z * w1.z + hv.w * w1.w;
            a2 += hv.x * w2.x + hv.y * w2.y + hv.z * w2.z + hv.w * w2.w;
            a3 += hv.x * w3.x + hv.y * w3.y + hv.z * w3.z + hv.w * w3.w;
        }
        // cached region (smem)
#pragma unroll
        for (int j = 0; j < 6; j++) {
            const int idx = lane + 32 * j;
            float4 hv = sh4[idx];
            float4 w0 = wc4[(wrow + 0) * KC4 + idx];
            float4 w1 = wc4[(wrow + 1) * KC4 + idx];
            float4 w2 = wc4[(wrow + 2) * KC4 + idx];
            float4 w3 = wc4[(wrow + 3) * KC4 + idx];
            a0 += hv.x * w0.x + hv.y * w0.y + hv.z * w0.z + hv.w * w0.w;
            a1 += hv.x * w1.x + hv.y * w1.y + hv.z * w1.z + hv.w * w1.w;
            a2 += hv.x * w2.x + hv.y * w2.y + hv.z * w2.z + hv.w * w2.w;
            a3 += hv.x * w3.x + hv.y * w3.y + hv.z * w3.z + hv.w * w3.w;
        }

#pragma unroll
        for (int o = 16; o > 0; o >>= 1) {
            a0 += __shfl_down_sync(0xffffffffu, a0, o);
            a1 += __shfl_down_sync(0xffffffffu, a1, o);
            a2 += __shfl_down_sync(0xffffffffu, a2, o);
            a3 += __shfl_down_sync(0xffffffffu, a3, o);
        }
        if (lane == 0) {
            sg[wrow + 0] = a0; sg[wrow + 1] = a1;
            sg[wrow + 2] = a2; sg[wrow + 3] = a3;
        }
        asm volatile("cp.async.wait_group 0;" ::: "memory");
        __syncthreads();

        // tail: 16 threads do argmax + gate math (pure smem)
        if (t < 16) {
            int lc = 0;
            {
                float bv = slog[0];
                for (int cc = 1; cc < ncand; cc++)
                    if (slog[cc] > bv) { bv = slog[cc]; lc = cc; }
            }
            const float* cp = scand + (s & 1) * 704 + lc * 64;
            float gi = sg[t]      + cp[t];
            float gf = sg[16 + t] + cp[16 + t];
            float gg = sg[32 + t] + cp[32 + t];
            float go = sg[48 + t] + cp[48 + t];
            float c2 = sigmoidf_(gf) * scell[t] + sigmoidf_(gi) * tanhf(gg);
            float h2 = sigmoidf_(go) * tanhf(c2);
            scell[t] = c2;
            sunit[t] = h2;
            __stcg(&g_h[parity][j0 + t], h2);
            if (s == 22) __stcg(&g_c[j0 + t], c2);
        }
        __syncthreads();

        // epilogue: decode partials from smem decoder rows
        int ncls;
        dec_for(s, dec_act, dec_block, ncls);
        if (warp < ncls) {
            float v = (lane < 16) ? sunit[lane] * sdec[(doff + warp) * 16 + lane] : 0.0f;
            v += __shfl_down_sync(0xffffffffu, v, 8);
            v += __shfl_down_sync(0xffffffffu, v, 4);
            v += __shfl_down_sync(0xffffffffu, v, 2);
            v += __shfl_down_sync(0xffffffffu, v, 1);
            if (lane == 0) __stcg(&g_part[pw][warp][bid], v);
        }

        // cp.async prefetch of next step's candidate rows (register-free)
        int nb_next = cand_base + ncand;
        if (s < 22) {
            float* dstb = scand + ((s + 1) & 1) * 704;
            int chunks = ncls * 16;
            for (int idx = t; idx < chunks; idx += NTHR) {
                int cd = idx >> 4, c4 = idx & 15;
                int g = c4 >> 2, qf = c4 & 3;
                cpasync16(dstb + cd * 64 + g * 16 + qf * 4,
                          &g_preR[nb_next + cd][(size_t)g * H + j0 + qf * 4]);
            }
        }
        asm volatile("cp.async.commit_group;" ::: "memory");

        cand_base = nb_next;
        ncand = ncls;
        doff += ncls;

        ++phase;
        gsync(phase * 4);
    }

    // ---- final argmax (step-22 decode partials, 4 classes) ----
    if (warp < 4) {
        const float* p = g_part[1][warp];
        float a = __ldcg(&p[lane]) + __ldcg(&p[lane + 32])
                + __ldcg(&p[lane + 64]) + __ldcg(&p[lane + 96]);
        a += __shfl_down_sync(0xffffffffu, a, 16);
        a += __shfl_down_sync(0xffffffffu, a, 8);
        a += __shfl_down_sync(0xffffffffu, a, 4);
        a += __shfl_down_sync(0xffffffffu, a, 2);
        a += __shfl_down_sync(0xffffffffu, a, 1);
        if (lane == 0) slog[warp] = a;
    }
    __syncthreads();

    int best = 0;
    {
        float bv = slog[0];
        for (int cc = 1; cc < 4; cc++)
            if (slog[cc] > bv) { bv = slog[cc]; best = cc; }
    }

    // ---- stage final h, c into smem (reuse wc4 region), then float4 output ----
    float* hbuf = dyn;          // [2048]
    float* cbuf = dyn + 2048;   // [2048]
    {
        float4* hb4 = (float4*)hbuf;
        float4* cb4 = (float4*)cbuf;
        hb4[t] = __ldcg(&((const float4*)g_h[0])[t]);
        cb4[t] = __ldcg(&((const float4*)g_c)[t]);
    }
    __syncthreads();

    const float fidx = (float)best;
    const long HB = (long)B * H;
    const long n4 = out_size >> 2;
    float4* out4 = (float4*)out;
    for (long i4 = (long)bid * NTHR + t; i4 < n4; i4 += (long)NBLK * NTHR) {
        long i = i4 << 2;
        float4 v;
        if (i < B) {
            v = make_float4(fidx, fidx, fidx, fidx);
        } else if (i < B + HB) {
            v = *(const float4*)&hbuf[(i - B) & (H - 1)];
        } else {
            v = *(const float4*)&cbuf[(i - B - HB) & (H - 1)];
        }
        __stcs(&out4[i4], v);
    }
    // tail elements if out_size not divisible by 4
    for (long i = (n4 << 2) + (long)bid * NTHR + t; i < out_size; i += (long)NBLK * NTHR) {
        float v;
        if (i < B)               v = fidx;
        else if (i < B + HB)     v = hbuf[(i - B) & (H - 1)];
        else if (i < B + 2 * HB) v = cbuf[(i - B - HB) & (H - 1)];
        else                     v = 0.0f;
        __stcs(out + i, v);
    }
}

// ---------------------------------------------------------------------------
extern "C" void kernel_launch(void* const* d_in, const int* in_sizes, int n_in,
                              void* d_out, int out_size) {
    (void)in_sizes; (void)n_in;
    const float* Wih       = (const float*)d_in[1];
    const float* Whh       = (const float*)d_in[2];
    const float* b_ih      = (const float*)d_in[3];
    const float* b_hh      = (const float*)d_in[4];
    const float* enc_act   = (const float*)d_in[5];
    const float* enc_block = (const float*)d_in[6];
    const float* dec_act   = (const float*)d_in[7];
    const float* dec_block = (const float*)d_in[8];

    static int attr_done = 0;
    if (!attr_done) {
        cudaFuncSetAttribute(k_persist, cudaFuncAttributeMaxDynamicSharedMemorySize, P_DSMEM);
        cudaFuncSetAttribute(k_pre, cudaFuncAttributeMaxDynamicSharedMemorySize, PRE_DSMEM);
        attr_done = 1;
    }

    k_init<<<1, 256>>>();
    k_gather<<<NROW, 256>>>(enc_act, enc_block);
    k_pre<<<128, 256, PRE_DSMEM>>>(Wih, b_ih, b_hh);
    k_reduce<<<448, 1024>>>();
    k_persist<<<NBLK, NTHR, P_DSMEM>>>(Whh, b_ih, b_hh, dec_act, dec_block,
                                       (float*)d_out, out_size);
}

// round 11
// speedup vs baseline: 1.1688x; 1.0357x over previous
#include <cuda_runtime.h>
#include <cstddef>
#include <cstdint>

#define H     2048
#define B     1024
#define NB    12
#define NROW  112
#define GATES 8192
#define NBLK  128                 // persistent blocks (1/SM)
#define NTHR  512
#define KC4   192                 // float4 k-prefix of each W_hh row in smem (j<6)
#define JR0   6                   // register-resident j range [JR0, JR1)
#define JR1   10
#define JS0   10                  // streamed j range [JS0, 16)

// persist dynamic smem layout (floats)
#define WC_F      (64 * KC4 * 4)
#define SCAND_F   (2 * 704)
#define SDEC_F    (114 * 16)
#define SH_OFF_F  (WC_F + SCAND_F + SDEC_F)
#define P_DSMEM   ((SH_OFF_F + 2048) * 4)       // 217728 B

// k_pre dynamic smem
#define PRE_W_F2   (256 * 17)
#define PRE_E_F2   (56 * 17)
#define PRE_DSMEM  ((PRE_W_F2 + PRE_E_F2) * 8)

// ---------------------------------------------------------------------------
__device__ __align__(16) float g_h[2][H];
__device__ __align__(16) float g_c[H];
__device__ __align__(16) float g_emb[NROW][H];
__device__ __align__(16) float g_pre[4][NROW][GATES];   // k-quarter partials
__device__ __align__(16) float g_preR[NROW][GATES];     // reduced (+biases)
__device__ float g_part[2][12][NBLK];
__device__ unsigned g_cnt[32 * 8];

__device__ __forceinline__ float sigmoidf_(float v) { return 1.0f / (1.0f + expf(-v)); }

__device__ __forceinline__ unsigned long long pk2(float a, float b) {
    unsigned long long p;
    asm("mov.b64 %0, {%1, %2};" : "=l"(p) : "f"(a), "f"(b));
    return p;
}
__device__ __forceinline__ void fma2(unsigned long long& d,
                                     unsigned long long a, unsigned long long b) {
    asm("fma.rn.f32x2 %0, %1, %2, %0;" : "+l"(d) : "l"(a), "l"(b));
}
__device__ __forceinline__ void unpk2(unsigned long long p, float& a, float& b) {
    asm("mov.b64 {%0, %1}, %2;" : "=f"(a), "=f"(b) : "l"(p));
}

__device__ __forceinline__ void cpasync16(const float* smem_dst, const float* gsrc) {
    uint32_t d = (uint32_t)__cvta_generic_to_shared(smem_dst);
    asm volatile("cp.async.cg.shared.global [%0], [%1], 16;" :: "r"(d), "l"(gsrc));
}

// ---------------------------------------------------------------------------
// Non-flushing grid barrier: 32 padded counters, NBLK/32 = 4 arrivals each.
// ---------------------------------------------------------------------------
__device__ __forceinline__ void gsync(unsigned target4) {
    __syncthreads();
    if (threadIdx.x == 0) {
        asm volatile("red.release.gpu.global.add.u32 [%0], %1;"
                     :: "l"(&g_cnt[(blockIdx.x & 31) * 8]), "r"(1u) : "memory");
    }
    if (threadIdx.x < 32) {
        const unsigned* cp = &g_cnt[threadIdx.x * 8];
        unsigned v;
        while (true) {
            asm volatile("ld.acquire.gpu.global.u32 %0, [%1];" : "=r"(v) : "l"(cp) : "memory");
            if (v >= target4) break;
            __nanosleep(40);
        }
    }
    __syncthreads();
}

__global__ void k_init() {
    if (threadIdx.x < 32 * 8) g_cnt[threadIdx.x] = 0u;
}

// ---------------------------------------------------------------------------
__global__ void k_gather(const float* __restrict__ enc_act,
                         const float* __restrict__ enc_block) {
    int r = blockIdx.x;
    int u = 1, base = 0, cnt = 4;
    while (u < 22 && r >= base + cnt) { base += cnt; ++u; cnt = (u & 1) ? 4 : (u >> 1); }
    const float* src;
    if (r >= base + cnt) {
        src = enc_act;
    } else {
        int o = r - base;
        if (u & 1) src = enc_act   + ((size_t)((u - 1) >> 1) * 4        + o) * H;
        else       src = enc_block + ((size_t)((u >> 1) - 1) * (NB - 1) + o) * H;
    }
    const float4* s4 = (const float4*)src;
    float4*       d4 = (float4*)g_emb[r];
    for (int i = threadIdx.x; i < H / 4; i += 256) d4[i] = s4[i];
}

// ---------------------------------------------------------------------------
// Precompute GEMM (packed f32x2): 256 blocks x 1 tile (2/SM for issue overlap).
// ---------------------------------------------------------------------------
__global__ __launch_bounds__(256)
void k_pre(const float* __restrict__ Wih,
           const float* __restrict__ b_ih, const float* __restrict__ b_hh) {
    extern __shared__ float2 dynp[];
    float2* Wt2 = dynp;
    float2* Es2 = dynp + PRE_W_F2;

    const int t = threadIdx.x, c = t & 31, r = t >> 5;

    const int tile = blockIdx.x;
    const int nb = tile & 31, mb = (tile >> 5) & 1, kb = tile >> 6;
    const int n_base = nb * 256, m_base = mb * 56, k_base = kb * 512;

    unsigned long long acc[7][8];
#pragma unroll
    for (int j = 0; j < 7; j++)
#pragma unroll
        for (int i = 0; i < 8; i++) acc[j][i] = 0ull;

    float4 wst[8];
    float4 est[2];
    {
        const float4* wsrc = (const float4*)(Wih + (size_t)(n_base + t) * H + k_base);
#pragma unroll
        for (int q = 0; q < 8; q++) wst[q] = __ldcg(&wsrc[q]);
#pragma unroll
        for (int x = 0; x < 2; x++) {
            int idx = t + 256 * x;
            if (idx < 448) {
                int row = idx >> 3, q = idx & 7;
                est[x] = *(const float4*)&g_emb[m_base + row][k_base + 4 * q];
            }
        }
    }

    for (int kt = 0; kt < 512; kt += 32) {
        {
            float2* wd = &Wt2[t * 17];
#pragma unroll
            for (int q = 0; q < 8; q++) {
                wd[2 * q + 0] = make_float2(wst[q].x, wst[q].y);
                wd[2 * q + 1] = make_float2(wst[q].z, wst[q].w);
            }
#pragma unroll
            for (int x = 0; x < 2; x++) {
                int idx = t + 256 * x;
                if (idx < 448) {
                    int row = idx >> 3, q = idx & 7;
                    Es2[row * 17 + 2 * q + 0] = make_float2(est[x].x, est[x].y);
                    Es2[row * 17 + 2 * q + 1] = make_float2(est[x].z, est[x].w);
                }
            }
        }
        __syncthreads();

        if (kt + 32 < 512) {
            const int k0 = k_base + kt + 32;
            const float4* wsrc = (const float4*)(Wih + (size_t)(n_base + t) * H + k0);
#pragma unroll
            for (int q = 0; q < 8; q++) wst[q] = __ldcg(&wsrc[q]);
#pragma unroll
            for (int x = 0; x < 2; x++) {
                int idx = t + 256 * x;
                if (idx < 448) {
                    int row = idx >> 3, q = idx & 7;
                    est[x] = *(const float4*)&g_emb[m_base + row][k0 + 4 * q];
                }
            }
        }

#pragma unroll
        for (int kk2 = 0; kk2 < 16; kk2++) {
            unsigned long long w2[8], e2[7];
#pragma unroll
            for (int i = 0; i < 8; i++)
                w2[i] = *(const unsigned long long*)&Wt2[(c + 32 * i) * 17 + kk2];
#pragma unroll
            for (int j = 0; j < 7; j++)
                e2[j] = *(const unsigned long long*)&Es2[(r * 7 + j) * 17 + kk2];
#pragma unroll
            for (int j = 0; j < 7; j++)
#pragma unroll
                for (int i = 0; i < 8; i++)
                    fma2(acc[j][i], w2[i], e2[j]);
        }
        __syncthreads();
    }

#pragma unroll
    for (int j = 0; j < 7; j++) {
        int m = m_base + r * 7 + j;
#pragma unroll
        for (int i = 0; i < 8; i++) {
            int n = n_base + c + 32 * i;
            float lo, hi;
            unpk2(acc[j][i], lo, hi);
            float v = lo + hi;
            if (kb == 0) v += b_ih[n] + b_hh[n];
            g_pre[kb][m][n] = v;
        }
    }
}

// ---------------------------------------------------------------------------
// Reduce the 4 k-quarter partials into g_preR (deterministic order).
// ---------------------------------------------------------------------------
__global__ __launch_bounds__(1024)
void k_reduce() {
    int i = blockIdx.x * 2048 + threadIdx.x;
#pragma unroll
    for (int q = 0; q < 2; q++, i += 1024) {
        int m = i >> 13, n = i & (GATES - 1);
        float v = ((g_pre[0][m][n] + g_pre[1][m][n]) + g_pre[2][m][n]) + g_pre[3][m][n];
        g_preR[m][n] = v;
    }
}

// ---------------------------------------------------------------------------
__device__ __forceinline__ const float* dec_for(int s, const float* da,
                                                const float* db, int& ncls) {
    if (s == 0) { ncls = 4; return da; }
    if (s & 1)  { int bid = (s + 1) >> 1; ncls = bid;
                  return db + (size_t)(bid - 1) * (NB - 1) * H; }
    ncls = 4; return da + (size_t)(s >> 1) * 4 * H;
}

// ---------------------------------------------------------------------------
// Persistent kernel: 128 blocks x 512 threads (1/SM, 128 regs/thread).
// Block owns 16 hidden units = 64 W_hh rows. Warp w owns rows 4w..4w+3.
// k-slices: j<6 smem (KC4), j in [6,10) REGISTER-RESIDENT across all steps,
// j in [10,16) streamed from L2 each step.
// ---------------------------------------------------------------------------
__global__ __launch_bounds__(NTHR, 1)
void k_persist(const float* __restrict__ Whh,
               const float* __restrict__ b_ih, const float* __restrict__ b_hh,
               const float* __restrict__ dec_act, const float* __restrict__ dec_block,
               float* __restrict__ out, int out_size) {
    extern __shared__ float dyn[];
    float4* wc4   = (float4*)dyn;                    // [64][KC4]
    float*  scand = dyn + WC_F;                      // [2][704]
    float*  sdec  = scand + SCAND_F;                 // [114][16]
    float4* sh4   = (float4*)(dyn + SH_OFF_F);       // [512] staged h

    __shared__ float sg[64];
    __shared__ float slog[12];
    __shared__ float sunit[16];
    __shared__ float scell[16];

    const int bid = blockIdx.x, t = threadIdx.x;
    const int lane = t & 31, warp = t >> 5;
    const int j0 = bid * 16;
    const float4* W4 = (const float4*)Whh;

    const int wrow = warp * 4;
    const int gte = warp >> 2;
    const int un0 = (warp & 3) * 4;
    const float4* wp0 = W4 + (size_t)(gte * H + j0 + un0 + 0) * (H / 4);
    const float4* wp1 = W4 + (size_t)(gte * H + j0 + un0 + 1) * (H / 4);
    const float4* wp2 = W4 + (size_t)(gte * H + j0 + un0 + 2) * (H / 4);
    const float4* wp3 = W4 + (size_t)(gte * H + j0 + un0 + 3) * (H / 4);

    // ---- startup loads ----
    for (int idx = t; idx < 64 * KC4; idx += NTHR) {
        int R = idx / KC4, q = idx - R * KC4;
        size_t grow = (size_t)((R >> 4) * H + j0 + (R & 15));
        wc4[R * KC4 + q] = __ldcg(&W4[grow * (H / 4) + q]);
    }
    for (int e = t; e < SDEC_F; e += NTHR) {
        int cr = e >> 4, u = e & 15;
        int off = 0, nc = 0;
        const float* dp = dec_act;
        for (int s = 0; s <= 22; s++) {
            dp = dec_for(s, dec_act, dec_block, nc);
            if (cr < off + nc) break;
            off += nc;
        }
        int cls = cr - off;
        sdec[e] = __ldcg(&dp[(size_t)cls * H + j0 + u]);
    }
    for (int idx = t; idx < 4 * 64; idx += NTHR) {
        int cd = idx >> 6, c = idx & 63;
        int g = c >> 4, u = c & 15;
        scand[704 + cd * 64 + c] = __ldcg(&g_preR[cd][(size_t)g * H + j0 + u]);
    }

    // register-resident W slice: rows wrow..wrow+3, j = JR0..JR1-1
    float4 wr0[JR1 - JR0], wr1[JR1 - JR0], wr2[JR1 - JR0], wr3[JR1 - JR0];
#pragma unroll
    for (int jj = 0; jj < JR1 - JR0; jj++) {
        const int idx = lane + 32 * (JR0 + jj);
        wr0[jj] = __ldcg(&wp0[idx]);
        wr1[jj] = __ldcg(&wp1[idx]);
        wr2[jj] = __ldcg(&wp2[idx]);
        wr3[jj] = __ldcg(&wp3[idx]);
    }

    // ---- step 0: gates = biases ----
    if (t < 16) {
        int j = j0 + t;
        float gi = b_ih[j        ] + b_hh[j        ];
        float gg = b_ih[2 * H + j] + b_hh[2 * H + j];
        float go = b_ih[3 * H + j] + b_hh[3 * H + j];
        float c2 = sigmoidf_(gi) * tanhf(gg);
        float h2 = sigmoidf_(go) * tanhf(c2);
        scell[t] = c2;
        sunit[t] = h2;
        __stcg(&g_h[0][j], h2);
    }
    __syncthreads();
    if (warp < 4) {
        float v = (lane < 16) ? sunit[lane] * sdec[warp * 16 + lane] : 0.0f;
        v += __shfl_down_sync(0xffffffffu, v, 8);
        v += __shfl_down_sync(0xffffffffu, v, 4);
        v += __shfl_down_sync(0xffffffffu, v, 2);
        v += __shfl_down_sync(0xffffffffu, v, 1);
        if (lane == 0) __stcg(&g_part[1][warp][bid], v);
    }

    unsigned phase = 1;
    gsync(phase * 4);

    // ---- 22 fused steps ----
    int cand_base = 0, ncand = 4, doff = 4;
    for (int s = 1; s <= 22; s++) {
        const int parity = s & 1, pr = s & 1, pw = (s + 1) & 1;

        // stage h into smem
        sh4[t] = __ldcg(&((const float4*)g_h[parity ^ 1])[t]);

        // prologue: per-class sums of 128 block-partials
        if (warp < ncand) {
            const float* p = g_part[pr][warp];
            float a = __ldcg(&p[lane]) + __ldcg(&p[lane + 32])
                    + __ldcg(&p[lane + 64]) + __ldcg(&p[lane + 96]);
            a += __shfl_down_sync(0xffffffffu, a, 16);
            a += __shfl_down_sync(0xffffffffu, a, 8);
            a += __shfl_down_sync(0xffffffffu, a, 4);
            a += __shfl_down_sync(0xffffffffu, a, 2);
            a += __shfl_down_sync(0xffffffffu, a, 1);
            if (lane == 0) slog[warp] = a;
        }
        __syncthreads();

        // GEMV: warp computes rows wrow..wrow+3 fully
        float a0 = 0.f, a1 = 0.f, a2 = 0.f, a3 = 0.f;

        // streamed region (j = JS0..15)
#pragma unroll
        for (int j = JS0; j < 16; j++) {
            const int idx = lane + 32 * j;
            float4 w0 = __ldcg(&wp0[idx]);
            float4 w1 = __ldcg(&wp1[idx]);
            float4 w2 = __ldcg(&wp2[idx]);
            float4 w3 = __ldcg(&wp3[idx]);
            float4 hv = sh4[idx];
            a0 += hv.x * w0.x + hv.y * w0.y + hv.z * w0.z + hv.w * w0.w;
            a1 += hv.x * w1.x + hv.y * w1.y + hv.z * w1.z + hv.w * w1.w;
            a2 += hv.x * w2.x + hv.y * w2.y + hv.z * w2.z + hv.w * w2.w;
            a3 += hv.x * w3.x + hv.y * w3.y + hv.z * w3.z + hv.w * w3.w;
        }
        // register-resident region (j = JR0..JR1-1)
#pragma unroll
        for (int jj = 0; jj < JR1 - JR0; jj++) {
            const int idx = lane + 32 * (JR0 + jj);
            float4 hv = sh4[idx];
            a0 += hv.x * wr0[jj].x + hv.y * wr0[jj].y + hv.z * wr0[jj].z + hv.w * wr0[jj].w;
            a1 += hv.x * wr1[jj].x + hv.y * wr1[jj].y + hv.z * wr1[jj].z + hv.w * wr1[jj].w;
            a2 += hv.x * wr2[jj].x + hv.y * wr2[jj].y + hv.z * wr2[jj].z + hv.w * wr2[jj].w;
            a3 += hv.x * wr3[jj].x + hv.y * wr3[jj].y + hv.z * wr3[jj].z + hv.w * wr3[jj].w;
        }
        // smem-cached region (j = 0..5)
#pragma unroll
        for (int j = 0; j < 6; j++) {
            const int idx = lane + 32 * j;
            float4 hv = sh4[idx];
            float4 w0 = wc4[(wrow + 0) * KC4 + idx];
            float4 w1 = wc4[(wrow + 1) * KC4 + idx];
            float4 w2 = wc4[(wrow + 2) * KC4 + idx];
            float4 w3 = wc4[(wrow + 3) * KC4 + idx];
            a0 += hv.x * w0.x + hv.y * w0.y + hv.z * w0.z + hv.w * w0.w;
            a1 += hv.x * w1.x + hv.y * w1.y + hv.z * w1.z + hv.w * w1.w;
            a2 += hv.x * w2.x + hv.y * w2.y + hv.z * w2.z + hv.w * w2.w;
            a3 += hv.x * w3.x + hv.y * w3.y + hv.z * w3.z + hv.w * w3.w;
        }

#pragma unroll
        for (int o = 16; o > 0; o >>= 1) {
            a0 += __shfl_down_sync(0xffffffffu, a0, o);
            a1 += __shfl_down_sync(0xffffffffu, a1, o);
            a2 += __shfl_down_sync(0xffffffffu, a2, o);
            a3 += __shfl_down_sync(0xffffffffu, a3, o);
        }
        if (lane == 0) {
            sg[wrow + 0] = a0; sg[wrow + 1] = a1;
            sg[wrow + 2] = a2; sg[wrow + 3] = a3;
        }
        asm volatile("cp.async.wait_group 0;" ::: "memory");
        __syncthreads();

        // tail: 16 threads do argmax + gate math (pure smem)
        if (t < 16) {
            int lc = 0;
            {
                float bv = slog[0];
                for (int cc = 1; cc < ncand; cc++)
                    if (slog[cc] > bv) { bv = slog[cc]; lc = cc; }
            }
            const float* cp = scand + (s & 1) * 704 + lc * 64;
            float gi = sg[t]      + cp[t];
            float gf = sg[16 + t] + cp[16 + t];
            float gg = sg[32 + t] + cp[32 + t];
            float go = sg[48 + t] + cp[48 + t];
            float c2 = sigmoidf_(gf) * scell[t] + sigmoidf_(gi) * tanhf(gg);
            float h2 = sigmoidf_(go) * tanhf(c2);
            scell[t] = c2;
            sunit[t] = h2;
            __stcg(&g_h[parity][j0 + t], h2);
            if (s == 22) __stcg(&g_c[j0 + t], c2);
        }
        __syncthreads();

        // epilogue: decode partials from smem decoder rows
        int ncls;
        dec_for(s, dec_act, dec_block, ncls);
        if (warp < ncls) {
            float v = (lane < 16) ? sunit[lane] * sdec[(doff + warp) * 16 + lane] : 0.0f;
            v += __shfl_down_sync(0xffffffffu, v, 8);
            v += __shfl_down_sync(0xffffffffu, v, 4);
            v += __shfl_down_sync(0xffffffffu, v, 2);
            v += __shfl_down_sync(0xffffffffu, v, 1);
            if (lane == 0) __stcg(&g_part[pw][warp][bid], v);
        }

        // cp.async prefetch of next step's candidate rows
        int nb_next = cand_base + ncand;
        if (s < 22) {
            float* dstb = scand + ((s + 1) & 1) * 704;
            int chunks = ncls * 16;
            for (int idx = t; idx < chunks; idx += NTHR) {
                int cd = idx >> 4, c4 = idx & 15;
                int g = c4 >> 2, qf = c4 & 3;
                cpasync16(dstb + cd * 64 + g * 16 + qf * 4,
                          &g_preR[nb_next + cd][(size_t)g * H + j0 + qf * 4]);
            }
        }
        asm volatile("cp.async.commit_group;" ::: "memory");

        cand_base = nb_next;
        ncand = ncls;
        doff += ncls;

        ++phase;
        gsync(phase * 4);
    }

    // ---- final argmax ----
    if (warp < 4) {
        const float* p = g_part[1][warp];
        float a = __ldcg(&p[lane]) + __ldcg(&p[lane + 32])
                + __ldcg(&p[lane + 64]) + __ldcg(&p[lane + 96]);
        a += __shfl_down_sync(0xffffffffu, a, 16);
        a += __shfl_down_sync(0xffffffffu, a, 8);
        a += __shfl_down_sync(0xffffffffu, a, 4);
        a += __shfl_down_sync(0xffffffffu, a, 2);
        a += __shfl_down_sync(0xffffffffu, a, 1);
        if (lane == 0) slog[warp] = a;
    }
    __syncthreads();

    int best = 0;
    {
        float bv = slog[0];
        for (int cc = 1; cc < 4; cc++)
            if (slog[cc] > bv) { bv = slog[cc]; best = cc; }
    }

    // ---- stage final h, c into smem (reuse wc4 region), then float4 output ----
    float* hbuf = dyn;
    float* cbuf = dyn + 2048;
    {
        float4* hb4 = (float4*)hbuf;
        float4* cb4 = (float4*)cbuf;
        hb4[t] = __ldcg(&((const float4*)g_h[0])[t]);
        cb4[t] = __ldcg(&((const float4*)g_c)[t]);
    }
    __syncthreads();

    const float fidx = (float)best;
    const long HB = (long)B * H;
    const long n4 = out_size >> 2;
    float4* out4 = (float4*)out;
    for (long i4 = (long)bid * NTHR + t; i4 < n4; i4 += (long)NBLK * NTHR) {
        long i = i4 << 2;
        float4 v;
        if (i < B) {
            v = make_float4(fidx, fidx, fidx, fidx);
        } else if (i < B + HB) {
            v = *(const float4*)&hbuf[(i - B) & (H - 1)];
        } else {
            v = *(const float4*)&cbuf[(i - B - HB) & (H - 1)];
        }
        __stcs(&out4[i4], v);
    }
    for (long i = (n4 << 2) + (long)bid * NTHR + t; i < out_size; i += (long)NBLK * NTHR) {
        float v;
        if (i < B)               v = fidx;
        else if (i < B + HB)     v = hbuf[(i - B) & (H - 1)];
        else if (i < B + 2 * HB) v = cbuf[(i - B - HB) & (H - 1)];
        else                     v = 0.0f;
        __stcs(out + i, v);
    }
}

// ---------------------------------------------------------------------------
extern "C" void kernel_launch(void* const* d_in, const int* in_sizes, int n_in,
                              void* d_out, int out_size) {
    (void)in_sizes; (void)n_in;
    const float* Wih       = (const float*)d_in[1];
    const float* Whh       = (const float*)d_in[2];
    const float* b_ih      = (const float*)d_in[3];
    const float* b_hh      = (const float*)d_in[4];
    const float* enc_act   = (const float*)d_in[5];
    const float* enc_block = (const float*)d_in[6];
    const float* dec_act   = (const float*)d_in[7];
    const float* dec_block = (const float*)d_in[8];

    static int attr_done = 0;
    if (!attr_done) {
        cudaFuncSetAttribute(k_persist, cudaFuncAttributeMaxDynamicSharedMemorySize, P_DSMEM);
        cudaFuncSetAttribute(k_pre, cudaFuncAttributeMaxDynamicSharedMemorySize, PRE_DSMEM);
        attr_done = 1;
    }

    k_init<<<1, 256>>>();
    k_gather<<<NROW, 256>>>(enc_act, enc_block);
    k_pre<<<256, 256, PRE_DSMEM>>>(Wih, b_ih, b_hh);
    k_reduce<<<448, 1024>>>();
    k_persist<<<NBLK, NTHR, P_DSMEM>>>(Whh, b_ih, b_hh, dec_act, dec_block,
                                       (float*)d_out, out_size);
}